// round 10
// baseline (speedup 1.0000x reference)
#include <cuda_runtime.h>
#include <cuda_bf16.h>
#include <cstdint>

#define DEVINL __device__ __forceinline__

// Shapes: score [2,16,2048,2048] f32, value [2,16,2048,128] f32 -> out [2,16,2048,128] f32
static constexpr int S_ = 2048;
static constexpr int D_ = 128;
static constexpr int BH = 32;
static constexpr int KB = 64;             // K per chunk
static constexpr int CHUNKS = S_ / KB;    // 32
static constexpr int MT = 64;             // CTA M tile
static constexpr int STAGES = 4;

// Padded smem rows: 64 bf16 + 8 pad = 144 bytes (ldmatrix conflict-free)
static constexpr int ROWB = 144;
static constexpr int A_BYTES = MT * ROWB;               // 9216
static constexpr int B_BYTES = 128 * ROWB;              // 18432
static constexpr int STAGE_BYTES = A_BYTES + B_BYTES;   // 27648
static constexpr int MBAR_OFF = STAGES * STAGE_BYTES;   // 110592
static constexpr int SMEM_TOTAL = MBAR_OFF + STAGES * 16;  // full/empty pairs

// Prequantized+transposed value: vt[bh][d][k] bf16, K contiguous (16 MB scratch)
__device__ __align__(16) __nv_bfloat16 g_vt[(size_t)BH * D_ * S_];

DEVINL uint32_t smem_u32(const void* p) {
    uint32_t a;
    asm("{ .reg .u64 t; cvta.to.shared.u64 t, %1; cvt.u32.u64 %0, t; }" : "=r"(a) : "l"(p));
    return a;
}

// Quantize: round-half-even(x/scale) clamped to [-129, 127] (faithful to reference)
DEVINL float quant1(float x, float inv) {
    return fminf(fmaxf(rintf(x * inv), -129.0f), 127.0f);
}
DEVINL uint32_t packq2(float a, float b, float inv) {
    __nv_bfloat162 h = __floats2bfloat162_rn(quant1(a, inv), quant1(b, inv));
    return *reinterpret_cast<uint32_t*>(&h);
}

DEVINL void cp_async16(uint32_t saddr, const void* gaddr) {
    asm volatile("cp.async.cg.shared.global [%0], [%1], 16;" :: "r"(saddr), "l"(gaddr));
}
DEVINL void cp_wait0() { asm volatile("cp.async.wait_all;" ::: "memory"); }

DEVINL void mbar_init(uint32_t addr, uint32_t cnt) {
    asm volatile("mbarrier.init.shared.b64 [%0], %1;" :: "r"(addr), "r"(cnt) : "memory");
}
DEVINL void mbar_arrive(uint32_t addr) {
    asm volatile("mbarrier.arrive.release.cta.shared::cta.b64 _, [%0];" :: "r"(addr) : "memory");
}
DEVINL void mbar_wait(uint32_t mbar, uint32_t parity) {
    asm volatile(
        "{\n\t.reg .pred P;\n\t"
        "WAIT_%=:\n\t"
        "mbarrier.try_wait.parity.acquire.cta.shared::cta.b64 P, [%0], %1, 0x989680;\n\t"
        "@P bra.uni DONE_%=;\n\t"
        "bra.uni WAIT_%=;\n\t"
        "DONE_%=:\n\t}"
        :: "r"(mbar), "r"(parity) : "memory");
}

DEVINL void ldm4(uint32_t& r0, uint32_t& r1, uint32_t& r2, uint32_t& r3, uint32_t addr) {
    asm volatile("ldmatrix.sync.aligned.m8n8.x4.shared.b16 {%0,%1,%2,%3}, [%4];"
                 : "=r"(r0), "=r"(r1), "=r"(r2), "=r"(r3) : "r"(addr));
}

DEVINL void mma16816(float* c, const uint32_t* a, uint32_t b0, uint32_t b1) {
    asm volatile(
        "mma.sync.aligned.m16n8k16.row.col.f32.bf16.bf16.f32 "
        "{%0,%1,%2,%3}, {%4,%5,%6,%7}, {%8,%9}, {%0,%1,%2,%3};"
        : "+f"(c[0]), "+f"(c[1]), "+f"(c[2]), "+f"(c[3])
        : "r"(a[0]), "r"(a[1]), "r"(a[2]), "r"(a[3]), "r"(b0), "r"(b1));
}

// ---------------------------------------------------------------------------
// Kernel 1: quantize + transpose value -> g_vt[bh][d][k]
// ---------------------------------------------------------------------------
__global__ void quant_transpose_v(const float* __restrict__ value,
                                  const float* __restrict__ ksc) {
    __shared__ __nv_bfloat16 tile[32][34];
    const float inv = 1.0f / ksc[0];
    const int bh = blockIdx.z;
    const int kt = blockIdx.x;
    const int dt = blockIdx.y;
    const int tx = threadIdx.x;
    const int ty = threadIdx.y;

    const float* vp = value + ((size_t)bh * S_ + (size_t)kt * 32) * D_ + dt * 32;
    #pragma unroll
    for (int j = 0; j < 4; j++) {
        int k = ty + 8 * j;
        tile[k][tx] = __float2bfloat16(quant1(vp[(size_t)k * D_ + tx], inv));
    }
    __syncthreads();
    __nv_bfloat16* op = g_vt + ((size_t)bh * D_ + (size_t)dt * 32) * S_ + kt * 32;
    #pragma unroll
    for (int j = 0; j < 4; j++) {
        int d = ty + 8 * j;
        op[(size_t)d * S_ + tx] = tile[tx][d];
    }
}

// ---------------------------------------------------------------------------
// Kernel 2: warp-specialized GEMM.
// 256 threads: warps 0-3 consumers (MMA), warps 4-7 producers (LDG+quant+STS,
// cp.async for B). Tile M64 x N128, 4-stage ring, full/empty mbarriers.
// ---------------------------------------------------------------------------
__global__ void __launch_bounds__(256, 2)
sqbmm_gemm(const float* __restrict__ score,
           const float* __restrict__ qsc,
           const float* __restrict__ ksc,
           float* __restrict__ out) {
    extern __shared__ char smem[];
    const uint32_t sb = smem_u32(smem);
    const int tid  = threadIdx.x;
    const int lane = tid & 31;
    const int w    = tid >> 5;
    const int bx   = blockIdx.x;
    const int bh   = bx >> 5;        // 32 M-tiles per (b,h)
    const int mblk = bx & 31;

    const float* arow = score + ((size_t)bh * S_ + (size_t)mblk * MT) * S_;
    const __nv_bfloat16* bbase = g_vt + (size_t)bh * D_ * S_;

    if (tid == 0) {
        #pragma unroll
        for (int s = 0; s < STAGES; s++) {
            mbar_init(sb + MBAR_OFF + s * 16, 1);      // full[s]
            mbar_init(sb + MBAR_OFF + s * 16 + 8, 1);  // empty[s]
        }
    }
    __syncthreads();

    auto stage_base = [&](int s) { return sb + (uint32_t)(s * STAGE_BYTES); };
    auto full_b  = [&](int s) { return sb + MBAR_OFF + (uint32_t)(s * 16); };
    auto empty_b = [&](int s) { return sb + MBAR_OFF + (uint32_t)(s * 16 + 8); };

    if (w >= 4) {
        // ------------------------- PRODUCER -------------------------
        const float inv_q = 1.0f / qsc[0];
        const int ptid = tid - 128;                 // 0..127

        float4 rawA[2][8];                          // double-buffered A staging

        auto ldgA = [&](int kt, float4* r) {
            const int kk = kt * KB;
            #pragma unroll
            for (int i = 0; i < 8; i++) {
                int idx = ptid + i * 128;
                int row = idx >> 4;                 // 0..63
                int c4  = idx & 15;                 // 0..15
                r[i] = *reinterpret_cast<const float4*>(arow + (size_t)row * S_ + kk + c4 * 4);
            }
        };
        auto stsA = [&](uint32_t stg, const float4* r) {
            #pragma unroll
            for (int i = 0; i < 8; i++) {
                int idx = ptid + i * 128;
                int row = idx >> 4;
                int c4  = idx & 15;
                uint32_t u0 = packq2(r[i].x, r[i].y, inv_q);
                uint32_t u1 = packq2(r[i].z, r[i].w, inv_q);
                asm volatile("st.shared.v2.b32 [%0], {%1,%2};"
                             :: "r"(stg + (uint32_t)(row * ROWB + c4 * 8)),
                                "r"(u0), "r"(u1) : "memory");
            }
        };
        // B: full 128x64bf16 tile = 1024 x 16B -> 8 per producer thread
        auto cp_b = [&](uint32_t stg, int kt) {
            const int kk = kt * KB;
            #pragma unroll
            for (int i = 0; i < 8; i++) {
                int idx = ptid + i * 128;
                int d = idx >> 3;                   // 0..127
                int c = idx & 7;                    // 0..7
                cp_async16(stg + A_BYTES + (uint32_t)(d * ROWB + c * 16),
                           bbase + (size_t)d * S_ + kk + c * 8);
            }
        };

        ldgA(0, rawA[0]);                            // chunk 0 A in flight early
        for (int c = 0; c < CHUNKS; c++) {
            const int s = c & 3;
            const uint32_t eph = (((unsigned)c >> 2) & 1u) ^ 1u;   // start phase 1
            if (c + 1 < CHUNKS) ldgA(c + 1, rawA[(c + 1) & 1]);    // DRAM, deep prefetch
            mbar_wait(empty_b(s), eph);              // stage free? (A loads fly meanwhile)
            const uint32_t stg = stage_base(s);
            cp_b(stg, c);                            // L2-resident B, async into smem
            stsA(stg, rawA[c & 1]);                  // quantize + store A
            cp_wait0();                              // B landed (covered by stsA work)
            asm volatile("bar.sync 1, 128;" ::: "memory");   // producers done (drains STS)
            if (tid == 128) mbar_arrive(full_b(s));
        }
    } else {
        // ------------------------- CONSUMER -------------------------
        // warp grid 2(m) x 2(n): warp tile 32 x 64
        const int wm = (w >> 1) * 32;
        const int wn = (w & 1) * 64;
        const uint32_t a_lm = (uint32_t)((wm + (lane & 15)) * ROWB + (lane >> 4) * 16);
        const uint32_t b_lm = (uint32_t)((wn + (lane & 7) + ((lane & 16) ? 8 : 0)) * ROWB
                                         + ((lane & 8) ? 16 : 0));

        float acc[2][8][4];
        #pragma unroll
        for (int i = 0; i < 2; i++)
            #pragma unroll
            for (int j = 0; j < 8; j++)
                #pragma unroll
                for (int k = 0; k < 4; k++) acc[i][j][k] = 0.0f;

        for (int c = 0; c < CHUNKS; c++) {
            const int s = c & 3;
            const uint32_t fph = ((unsigned)c >> 2) & 1u;
            mbar_wait(full_b(s), fph);
            const uint32_t base  = stage_base(s);
            const uint32_t aaddr = base + a_lm;
            const uint32_t baddr = base + A_BYTES + b_lm;
            #pragma unroll
            for (int ks = 0; ks < 4; ks++) {
                uint32_t a[2][4];
                #pragma unroll
                for (int mt = 0; mt < 2; mt++)
                    ldm4(a[mt][0], a[mt][1], a[mt][2], a[mt][3],
                         aaddr + (uint32_t)(mt * 16 * ROWB + ks * 32));
                uint32_t b[4][4];
                #pragma unroll
                for (int np = 0; np < 4; np++)
                    ldm4(b[np][0], b[np][1], b[np][2], b[np][3],
                         baddr + (uint32_t)(np * 16 * ROWB + ks * 32));
                #pragma unroll
                for (int mt = 0; mt < 2; mt++)
                    #pragma unroll
                    for (int nt = 0; nt < 8; nt++)
                        mma16816(acc[mt][nt], a[mt], b[nt >> 1][(nt & 1) * 2],
                                 b[nt >> 1][(nt & 1) * 2 + 1]);
            }
            asm volatile("bar.sync 2, 128;" ::: "memory");   // all consumers done reading
            if (tid == 0) mbar_arrive(empty_b(s));
        }

        // Epilogue: scale + store
        const float fs = qsc[0] * ksc[0];
        float* outp = out + ((size_t)bh * S_ + (size_t)mblk * MT) * D_;
        #pragma unroll
        for (int mt = 0; mt < 2; mt++) {
            const int r0 = wm + mt * 16 + (lane >> 2);
            #pragma unroll
            for (int nt = 0; nt < 8; nt++) {
                const int col = wn + nt * 8 + (lane & 3) * 2;
                float2 v0 = make_float2(acc[mt][nt][0] * fs, acc[mt][nt][1] * fs);
                float2 v1 = make_float2(acc[mt][nt][2] * fs, acc[mt][nt][3] * fs);
                *reinterpret_cast<float2*>(outp + (size_t)r0 * D_ + col) = v0;
                *reinterpret_cast<float2*>(outp + (size_t)(r0 + 8) * D_ + col) = v1;
            }
        }
    }
}

// ---------------------------------------------------------------------------
extern "C" void kernel_launch(void* const* d_in, const int* in_sizes, int n_in,
                              void* d_out, int out_size) {
    const float* score = (const float*)d_in[0];
    const float* value = (const float*)d_in[1];
    const float* qsc   = (const float*)d_in[2];
    const float* ksc   = (const float*)d_in[3];
    float* out = (float*)d_out;
    (void)in_sizes; (void)n_in; (void)out_size;

    dim3 g1(S_ / 32, D_ / 32, BH);
    dim3 b1(32, 8);
    quant_transpose_v<<<g1, b1>>>(value, ksc);

    cudaFuncSetAttribute(sqbmm_gemm, cudaFuncAttributeMaxDynamicSharedMemorySize, SMEM_TOTAL);
    sqbmm_gemm<<<BH * (S_ / MT), 256, SMEM_TOTAL>>>(score, qsc, ksc, out);
}

// round 11
// speedup vs baseline: 1.2001x; 1.2001x over previous
#include <cuda_runtime.h>
#include <cuda_bf16.h>
#include <cstdint>

#define DEVINL __device__ __forceinline__

// Shapes: score [2,16,2048,2048] f32, value [2,16,2048,128] f32 -> out [2,16,2048,128] f32
static constexpr int S_ = 2048;
static constexpr int D_ = 128;
static constexpr int BH = 32;
static constexpr int KB = 32;              // K per chunk
static constexpr int CHUNKS = S_ / KB;     // 64
static constexpr int STAGES = 6;

// fp32 A stage: 128 rows x 32 f32 = 128B rows
static constexpr int AF_BYTES = 128 * 128;             // 16384
// B stage: 128 rows x 32 bf16 = 64B data, padded to 80B (ldmatrix conflict-free)
static constexpr int ROWB = 80;
static constexpr int B_BYTES = 128 * ROWB;             // 10240
static constexpr int STAGE_BYTES = AF_BYTES + B_BYTES; // 26624
// bf16 A buffer (double): 128 rows x 80B
static constexpr int ABUF_BYTES = 128 * ROWB;          // 10240
static constexpr int ABUF_OFF = STAGES * STAGE_BYTES;  // 159744
static constexpr int SMEM_TOTAL = ABUF_OFF + 2 * ABUF_BYTES;  // 180224

// Prequantized+transposed value: vt[bh][d][k] bf16, K contiguous (16 MB scratch)
__device__ __align__(16) __nv_bfloat16 g_vt[(size_t)BH * D_ * S_];

DEVINL uint32_t smem_u32(const void* p) {
    uint32_t a;
    asm("{ .reg .u64 t; cvta.to.shared.u64 t, %1; cvt.u32.u64 %0, t; }" : "=r"(a) : "l"(p));
    return a;
}

// Quantize: round-half-even(x/scale) clamped to [-129, 127] (faithful to reference)
DEVINL float quant1(float x, float inv) {
    return fminf(fmaxf(rintf(x * inv), -129.0f), 127.0f);
}
DEVINL uint32_t packq2(float a, float b, float inv) {
    __nv_bfloat162 h = __floats2bfloat162_rn(quant1(a, inv), quant1(b, inv));
    return *reinterpret_cast<uint32_t*>(&h);
}

DEVINL void cp_async16(uint32_t saddr, const void* gaddr) {
    asm volatile("cp.async.cg.shared.global [%0], [%1], 16;" :: "r"(saddr), "l"(gaddr));
}
DEVINL void cp_commit() { asm volatile("cp.async.commit_group;"); }
template <int N> DEVINL void cp_wait() {
    asm volatile("cp.async.wait_group %0;" :: "n"(N) : "memory");
}

DEVINL void ldm4(uint32_t& r0, uint32_t& r1, uint32_t& r2, uint32_t& r3, uint32_t addr) {
    asm volatile("ldmatrix.sync.aligned.m8n8.x4.shared.b16 {%0,%1,%2,%3}, [%4];"
                 : "=r"(r0), "=r"(r1), "=r"(r2), "=r"(r3) : "r"(addr));
}

DEVINL void mma16816(float* c, const uint32_t* a, uint32_t b0, uint32_t b1) {
    asm volatile(
        "mma.sync.aligned.m16n8k16.row.col.f32.bf16.bf16.f32 "
        "{%0,%1,%2,%3}, {%4,%5,%6,%7}, {%8,%9}, {%0,%1,%2,%3};"
        : "+f"(c[0]), "+f"(c[1]), "+f"(c[2]), "+f"(c[3])
        : "r"(a[0]), "r"(a[1]), "r"(a[2]), "r"(a[3]), "r"(b0), "r"(b1));
}

// ---------------------------------------------------------------------------
// Kernel 1: quantize + transpose value -> g_vt[bh][d][k]
// ---------------------------------------------------------------------------
__global__ void quant_transpose_v(const float* __restrict__ value,
                                  const float* __restrict__ ksc) {
    __shared__ __nv_bfloat16 tile[32][34];
    const float inv = 1.0f / ksc[0];
    const int bh = blockIdx.z;
    const int kt = blockIdx.x;
    const int dt = blockIdx.y;
    const int tx = threadIdx.x;
    const int ty = threadIdx.y;

    const float* vp = value + ((size_t)bh * S_ + (size_t)kt * 32) * D_ + dt * 32;
    #pragma unroll
    for (int j = 0; j < 4; j++) {
        int k = ty + 8 * j;
        tile[k][tx] = __float2bfloat16(quant1(vp[(size_t)k * D_ + tx], inv));
    }
    __syncthreads();
    __nv_bfloat16* op = g_vt + ((size_t)bh * D_ + (size_t)dt * 32) * S_ + kt * 32;
    #pragma unroll
    for (int j = 0; j < 4; j++) {
        int d = ty + 8 * j;
        op[(size_t)d * S_ + tx] = tile[tx][d];
    }
}

// ---------------------------------------------------------------------------
// Kernel 2: monolithic GEMM, register-free A path.
// fp32 score -> smem via 6-stage cp.async ring (wait_group 3 => ~4 chunks of
// latency cover). Quantize smem->smem one chunk ahead of MMA. One barrier/chunk.
// CTA: 256 threads, tile M128 x N128, warp tile 64x32.
// ---------------------------------------------------------------------------
__global__ void __launch_bounds__(256, 1)
sqbmm_gemm(const float* __restrict__ score,
           const float* __restrict__ qsc,
           const float* __restrict__ ksc,
           float* __restrict__ out) {
    extern __shared__ char smem[];
    const uint32_t sb = smem_u32(smem);
    const int tid  = threadIdx.x;
    const int lane = tid & 31;
    const int w    = tid >> 5;
    const int bx   = blockIdx.x;
    const int bh   = bx >> 4;
    const int mblk = bx & 15;

    const float inv_q = 1.0f / qsc[0];
    const float* arow = score + ((size_t)bh * S_ + (size_t)mblk * 128) * S_;
    const __nv_bfloat16* bbase = g_vt + (size_t)bh * D_ * S_;

    auto stageA = [&](int s) { return sb + (uint32_t)(s * STAGE_BYTES); };
    auto stageB = [&](int s) { return sb + (uint32_t)(s * STAGE_BYTES + AF_BYTES); };
    auto abuf   = [&](int p) { return sb + (uint32_t)(ABUF_OFF + p * ABUF_BYTES); };

    // Issue cp.async for chunk c into stage c%STAGES (A fp32 + B bf16), 1 commit.
    auto issue = [&](int c) {
        const int kk = c * KB;
        const int s  = c % STAGES;
        const uint32_t sA = stageA(s);
        const uint32_t sB = stageB(s);
        // A: 128 rows x 128B = 1024 x 16B -> 4 per thread
        #pragma unroll
        for (int i = 0; i < 4; i++) {
            int idx = tid + i * 256;
            int row = idx >> 3;
            int cc  = idx & 7;
            cp_async16(sA + (uint32_t)(row * 128 + cc * 16),
                       arow + (size_t)row * S_ + kk + cc * 4);
        }
        // B: 128 rows x 64B = 512 x 16B -> 2 per thread
        #pragma unroll
        for (int i = 0; i < 2; i++) {
            int idx = tid + i * 256;
            int d  = idx >> 2;
            int cc = idx & 3;
            cp_async16(sB + (uint32_t)(d * ROWB + cc * 16),
                       bbase + (size_t)d * S_ + kk + cc * 8);
        }
    };

    // Quantize fp32 stage -> bf16 buffer. Source is smem: short latency chain.
    auto convert = [&](int c) {
        const uint32_t src = stageA(c % STAGES);
        const uint32_t dst = abuf(c & 1);
        #pragma unroll
        for (int i = 0; i < 4; i++) {
            int idx = tid + i * 256;
            int row = idx >> 3;
            int c4  = idx & 7;
            float x0, x1, x2, x3;
            asm volatile("ld.shared.v4.f32 {%0,%1,%2,%3}, [%4];"
                         : "=f"(x0), "=f"(x1), "=f"(x2), "=f"(x3)
                         : "r"(src + (uint32_t)(row * 128 + c4 * 16)));
            uint32_t u0 = packq2(x0, x1, inv_q);
            uint32_t u1 = packq2(x2, x3, inv_q);
            asm volatile("st.shared.v2.b32 [%0], {%1,%2};"
                         :: "r"(dst + (uint32_t)(row * ROWB + c4 * 8)),
                            "r"(u0), "r"(u1) : "memory");
        }
    };

    // warp tile: 64(m) x 32(n); warp grid 2x4
    const int wm = (w >> 2) * 64;
    const int wn = (w & 3) * 32;
    const uint32_t a_lm = (uint32_t)((wm + (lane & 15)) * ROWB + (lane >> 4) * 16);
    const uint32_t b_lm = (uint32_t)((wn + (lane & 7) + ((lane & 16) ? 8 : 0)) * ROWB
                                     + ((lane & 8) ? 16 : 0));

    float acc[4][4][4];
    #pragma unroll
    for (int i = 0; i < 4; i++)
        #pragma unroll
        for (int j = 0; j < 4; j++)
            #pragma unroll
            for (int k = 0; k < 4; k++) acc[i][j][k] = 0.0f;

    auto mma_chunk = [&](int c) {
        const uint32_t aaddr = abuf(c & 1) + a_lm;
        const uint32_t baddr = stageB(c % STAGES) + b_lm;
        #pragma unroll
        for (int ks = 0; ks < 2; ks++) {
            uint32_t a[4][4];
            #pragma unroll
            for (int mt = 0; mt < 4; mt++)
                ldm4(a[mt][0], a[mt][1], a[mt][2], a[mt][3],
                     aaddr + (uint32_t)(mt * 16 * ROWB + ks * 32));
            uint32_t b[2][4];
            #pragma unroll
            for (int np = 0; np < 2; np++)
                ldm4(b[np][0], b[np][1], b[np][2], b[np][3],
                     baddr + (uint32_t)(np * 16 * ROWB + ks * 32));
            #pragma unroll
            for (int mt = 0; mt < 4; mt++)
                #pragma unroll
                for (int nt = 0; nt < 4; nt++)
                    mma16816(acc[mt][nt], a[mt], b[nt >> 1][(nt & 1) * 2],
                             b[nt >> 1][(nt & 1) * 2 + 1]);
        }
    };

    // Prologue: issue chunks 0..4 (5 groups), convert chunk 0.
    #pragma unroll
    for (int p = 0; p < 5; p++) { issue(p); cp_commit(); }
    cp_wait<4>();         // chunk 0 landed
    __syncthreads();
    convert(0);

    // Main loop. Invariant at top of iter kt: groups 0..kt+4 committed.
    // wait_group 3 => chunk kt+1 complete (issued 4 iterations earlier).
    for (int kt = 0; kt < CHUNKS; kt++) {
        cp_wait<3>();
        __syncthreads();  // publish: stage kt+1 fp32+B, abuf((kt)&1) conversions,
                          // and all warps done reading stage (kt+5)%6's old data
        if (kt + 5 < CHUNKS) issue(kt + 5);
        cp_commit();      // exactly one group per iteration (possibly empty)
        if (kt + 1 < CHUNKS) convert(kt + 1);
        mma_chunk(kt);
    }

    // Epilogue: scale + store
    const float fs = qsc[0] * ksc[0];
    float* outp = out + ((size_t)bh * S_ + (size_t)mblk * 128) * D_;
    #pragma unroll
    for (int mt = 0; mt < 4; mt++) {
        const int r0 = wm + mt * 16 + (lane >> 2);
        #pragma unroll
        for (int nt = 0; nt < 4; nt++) {
            const int col = wn + nt * 8 + (lane & 3) * 2;
            float2 v0 = make_float2(acc[mt][nt][0] * fs, acc[mt][nt][1] * fs);
            float2 v1 = make_float2(acc[mt][nt][2] * fs, acc[mt][nt][3] * fs);
            *reinterpret_cast<float2*>(outp + (size_t)r0 * D_ + col) = v0;
            *reinterpret_cast<float2*>(outp + (size_t)(r0 + 8) * D_ + col) = v1;
        }
    }
}

// ---------------------------------------------------------------------------
extern "C" void kernel_launch(void* const* d_in, const int* in_sizes, int n_in,
                              void* d_out, int out_size) {
    const float* score = (const float*)d_in[0];
    const float* value = (const float*)d_in[1];
    const float* qsc   = (const float*)d_in[2];
    const float* ksc   = (const float*)d_in[3];
    float* out = (float*)d_out;
    (void)in_sizes; (void)n_in; (void)out_size;

    dim3 g1(S_ / 32, D_ / 32, BH);
    dim3 b1(32, 8);
    quant_transpose_v<<<g1, b1>>>(value, ksc);

    cudaFuncSetAttribute(sqbmm_gemm, cudaFuncAttributeMaxDynamicSharedMemorySize, SMEM_TOTAL);
    sqbmm_gemm<<<BH * (S_ / 128), 256, SMEM_TOTAL>>>(score, qsc, ksc, out);
}